// round 2
// baseline (speedup 1.0000x reference)
#include <cuda_runtime.h>

// MinimalRSNN: GLIF3 + AlphaPSC recurrent SNN.
//   Phase A: I_ext = x @ W_in^T          (fp32 tiled SGEMM, parallel)
//   Phase B: persistent 1000-step scan   (128 CTAs, 1 grid barrier/step)
//   Phase C: out = (spike_rate) @ W_out^T
//
// Scan layout: CTA c owns h in [8c, 8c+8) for ALL 32 batches; thread (b,hl)
// owns full neuron state in registers. Spikes exchanged as bytes via a
// double-buffered global array; one hand-rolled grid sync per step
// (128 CTAs <= 148 SMs -> co-resident, no cooperative launch needed).

#define T_STEPS 1000
#define BATCH   32
#define NI      512
#define NH      1024
#define NO      256

#define V_TH   (-45.0f)
#define V_RST  (-60.0f)
#define D_SYN  0.8187307530779818f   // exp(-1/5)
#define D_A0   0.9048374180359595f   // exp(-0.1)
#define D_A1   0.8187307530779818f   // exp(-0.2)
#define REF_T  2.0f

#define NBLK  128
#define SLICE 8
#define KC    256

// -------- device scratch (no allocations allowed) --------
__device__ float        g_Iext[(size_t)T_STEPS * BATCH * NH];   // 131 MB
__device__ unsigned int g_spk[2][BATCH * NH / 4];               // spike bytes, double-buffered
__device__ float        g_rate[BATCH * NH];
__device__ unsigned int g_bar;

__global__ void init_kernel() { g_bar = 0u; }

// -------- Phase A: C[M,N] = A[M,K] * B[N,K]^T (fp32) --------
#define BM 64
#define BN 64
#define BK 16
__global__ __launch_bounds__(256) void gemm_in_kernel(const float* __restrict__ A,
                                                      const float* __restrict__ Bm) {
    __shared__ float As[BK][BM + 4];
    __shared__ float Bs[BK][BN + 4];
    const int tid = threadIdx.x;
    const int tx = tid & 15, ty = tid >> 4;
    const int m0 = blockIdx.y * BM, n0 = blockIdx.x * BN;
    const int lr = tid >> 2;   // 0..63
    const int lq = tid & 3;    // 0..3
    float acc[4][4] = {};
    for (int kc = 0; kc < NI; kc += BK) {
        float4 a = *(const float4*)&A [(size_t)(m0 + lr) * NI + kc + lq * 4];
        float4 b = *(const float4*)&Bm[(size_t)(n0 + lr) * NI + kc + lq * 4];
        As[lq*4+0][lr] = a.x; As[lq*4+1][lr] = a.y; As[lq*4+2][lr] = a.z; As[lq*4+3][lr] = a.w;
        Bs[lq*4+0][lr] = b.x; Bs[lq*4+1][lr] = b.y; Bs[lq*4+2][lr] = b.z; Bs[lq*4+3][lr] = b.w;
        __syncthreads();
#pragma unroll
        for (int k = 0; k < BK; k++) {
            float4 av = *(const float4*)&As[k][ty * 4];
            float4 bv = *(const float4*)&Bs[k][tx * 4];
            float aa[4] = {av.x, av.y, av.z, av.w};
            float bb[4] = {bv.x, bv.y, bv.z, bv.w};
#pragma unroll
            for (int i = 0; i < 4; i++)
#pragma unroll
                for (int j = 0; j < 4; j++) acc[i][j] += aa[i] * bb[j];
        }
        __syncthreads();
    }
#pragma unroll
    for (int i = 0; i < 4; i++) {
        float4 v = {acc[i][0], acc[i][1], acc[i][2], acc[i][3]};
        *(float4*)&g_Iext[(size_t)(m0 + ty*4 + i) * NH + n0 + tx*4] = v;
    }
}

// -------- grid barrier (all NBLK CTAs co-resident) --------
__device__ __forceinline__ void grid_sync(int step) {
    __syncthreads();
    if (threadIdx.x == 0) {
        __threadfence();                       // release prior spike writes
        atomicAdd(&g_bar, 1u);
        const unsigned target = (unsigned)(step + 1) * NBLK;
        unsigned cur;
        do {
            asm volatile("ld.global.acquire.gpu.u32 %0, [%1];"
                         : "=r"(cur) : "l"(&g_bar));
        } while (cur < target);
    }
    __syncthreads();
}

// -------- Phase B: persistent scan --------
__global__ __launch_bounds__(256, 1) void scan_kernel(const float* __restrict__ Wrec) {
    __shared__ float sp_s[BATCH][KC];        // 32 KB spike tile (floats 0/1)
    __shared__ float wt_s[SLICE][KC + 4];    // 8.3 KB weight tile

    const int tid = threadIdx.x;
    const int b  = tid >> 3;      // 0..31
    const int hl = tid & 7;       // 0..7
    const int c  = blockIdx.x;    // h-slice id
    const int h  = c * SLICE + hl;

    float v = V_RST, a0 = 0.f, a1 = 0.f, ref = 0.f, hs = 0.f, psc = 0.f;
    int cnt = 0;

    for (int t = 0; t < T_STEPS; t++) {
        if (t > 0) {
            const unsigned int* spw = g_spk[(t - 1) & 1];
            float rec = 0.f;
            for (int kc = 0; kc < NH; kc += KC) {
                // stage spike bytes -> floats (bypass L1: data changes under the barrier)
#pragma unroll
                for (int i = 0; i < 8; i++) {
                    int w  = tid + i * 256;
                    int bb = w >> 6;
                    int jw = w & 63;
                    unsigned int val = __ldcg(&spw[bb * (NH/4) + (kc >> 2) + jw]);
                    sp_s[bb][jw * 4 + 0] = (float)( val        & 1u);
                    sp_s[bb][jw * 4 + 1] = (float)((val >>  8) & 1u);
                    sp_s[bb][jw * 4 + 2] = (float)((val >> 16) & 1u);
                    sp_s[bb][jw * 4 + 3] = (float)((val >> 24) & 1u);
                }
                // stage W_rec rows (L1-resident across steps)
#pragma unroll
                for (int i = 0; i < 2; i++) {
                    int q   = tid + i * 256;
                    int row = q >> 6;
                    int j4  = q & 63;
                    float4 wv = *(const float4*)&Wrec[(size_t)(c * SLICE + row) * NH + kc + j4 * 4];
                    *(float4*)&wt_s[row][j4 * 4] = wv;
                }
                __syncthreads();
                const float* sr = sp_s[b];
                const float* wr = wt_s[hl];
                float r0 = 0.f, r1 = 0.f, r2 = 0.f, r3 = 0.f;
#pragma unroll 16
                for (int j = 0; j < KC; j += 4) {
                    float4 s = *(const float4*)(sr + j);
                    float4 w = *(const float4*)(wr + j);
                    r0 += s.x * w.x; r1 += s.y * w.y;
                    r2 += s.z * w.z; r3 += s.w * w.w;
                }
                rec += (r0 + r1) + (r2 + r3);
                __syncthreads();
            }
            hs  = D_SYN * hs + rec;
            psc = D_SYN * psc + hs;          // DT = 1
        }

        // GLIF3 neuron update (all state in registers)
        float I = g_Iext[((size_t)t * BATCH + b) * NH + h] + psc;
        a0 *= D_A0;
        a1 *= D_A1;
        v = v + ((V_RST - v) * (1.0f / 20.0f) + (I + a0 + a1) * 0.5f);
        bool in_ref = ref > 0.0f;
        if (in_ref) v = V_RST;
        float spike = (!in_ref && v >= V_TH) ? 1.0f : 0.0f;
        if (spike > 0.0f) {
            v = V_RST; a0 += 1.0f; a1 -= 2.0f; ref = REF_T; cnt++;
        } else {
            ref = fmaxf(ref - 1.0f, 0.0f);
        }
        ((unsigned char*)g_spk[t & 1])[b * NH + h] = (unsigned char)spike;

        grid_sync(t);
    }
    g_rate[b * NH + h] = (float)cnt / 1000.0f;
}

// -------- Phase C: out[b,o] = rate[b,:] . W_out[o,:] --------
__global__ __launch_bounds__(256) void out_kernel(const float* __restrict__ Wout,
                                                  float* __restrict__ out) {
    int gw   = (blockIdx.x * blockDim.x + threadIdx.x) >> 5;
    int lane = threadIdx.x & 31;
    int b = gw >> 8;
    int o = gw & 255;
    const float* r = &g_rate[b * NH];
    const float* w = &Wout[(size_t)o * NH];
    float s = 0.f;
    for (int hh = lane; hh < NH; hh += 32) s += r[hh] * w[hh];
#pragma unroll
    for (int off = 16; off; off >>= 1) s += __shfl_down_sync(0xffffffffu, s, off);
    if (lane == 0) out[b * NO + o] = s;
}

// -------- launch --------
extern "C" void kernel_launch(void* const* d_in, const int* in_sizes, int n_in,
                              void* d_out, int out_size) {
    // Identify inputs by element count (robust to ordering).
    const float* x = nullptr;     // 16384000
    const float* W_in = nullptr;  // 524288
    const float* W_rec = nullptr; // 1048576
    const float* W_out = nullptr; // 262144
    for (int i = 0; i < n_in; i++) {
        switch (in_sizes[i]) {
            case T_STEPS * BATCH * NI: x     = (const float*)d_in[i]; break;
            case NH * NI:              W_in  = (const float*)d_in[i]; break;
            case NH * NH:              W_rec = (const float*)d_in[i]; break;
            case NO * NH:              W_out = (const float*)d_in[i]; break;
        }
    }
    float* out = (float*)d_out;

    init_kernel<<<1, 1>>>();

    dim3 g1(NH / BN, (T_STEPS * BATCH) / BM);   // (16, 500)
    gemm_in_kernel<<<g1, 256>>>(x, W_in);

    scan_kernel<<<NBLK, 256>>>(W_rec);

    out_kernel<<<(BATCH * NO * 32) / 256, 256>>>(W_out, out);
}

// round 3
// speedup vs baseline: 2.7771x; 2.7771x over previous
#include <cuda_runtime.h>

// MinimalRSNN: GLIF3 + AlphaPSC recurrent SNN.
//   Phase A: I_ext = x @ W_in^T      (fp32 SGEMM, 128x128x8, 8x8 reg tile)
//   Phase B: persistent 1000-step scan, 128 CTAs, 1 grid barrier/step
//            recurrent GEMM: warp-level 4b x 8h register tiles, K-split 32,
//            spikes (floats) streamed from L2, W_rec slice resident in smem
//   Phase C: out = spike_rate @ W_out^T

#define T_STEPS 1000
#define BATCH   32
#define NI      512
#define NH      1024
#define NO      256

#define V_TH   (-45.0f)
#define V_RST  (-60.0f)
#define D_SYN  0.8187307530779818f   // exp(-1/5)
#define D_A0   0.9048374180359595f   // exp(-0.1)
#define D_A1   0.8187307530779818f   // exp(-0.2)

#define NBLK  128

// -------- device scratch (no allocations allowed) --------
__device__ float        g_Iext[(size_t)T_STEPS * BATCH * NH];   // 131 MB
__device__ float        g_spkf[2][BATCH * NH];                  // spikes as floats, double-buffered
__device__ float        g_rate[BATCH * NH];
__device__ unsigned int g_bar;

__global__ void init_kernel() { g_bar = 0u; }

// -------- Phase A: C[M,N] = A[M,K] * B[N,K]^T (fp32, 128x128x8) --------
#define BM 128
#define BN 128
#define BK 8
__global__ __launch_bounds__(256) void gemm_in_kernel(const float* __restrict__ A,
                                                      const float* __restrict__ Bm) {
    __shared__ float As[BK][BM];
    __shared__ float Bs[BK][BN];
    const int tid = threadIdx.x;
    const int m0 = blockIdx.y * BM, n0 = blockIdx.x * BN;
    const int lr = tid >> 1;          // 0..127
    const int lc = (tid & 1) * 4;     // 0 or 4
    const int tx = tid & 15, ty = tid >> 4;
    float acc[8][8] = {};
    for (int kc = 0; kc < NI; kc += BK) {
        float4 av = *(const float4*)&A [(size_t)(m0 + lr) * NI + kc + lc];
        float4 bv = *(const float4*)&Bm[(size_t)(n0 + lr) * NI + kc + lc];
        As[lc + 0][lr] = av.x; As[lc + 1][lr] = av.y;
        As[lc + 2][lr] = av.z; As[lc + 3][lr] = av.w;
        Bs[lc + 0][lr] = bv.x; Bs[lc + 1][lr] = bv.y;
        Bs[lc + 2][lr] = bv.z; Bs[lc + 3][lr] = bv.w;
        __syncthreads();
#pragma unroll
        for (int k = 0; k < BK; k++) {
            float4 a0 = *(const float4*)&As[k][ty * 8];
            float4 a1 = *(const float4*)&As[k][ty * 8 + 4];
            float4 b0 = *(const float4*)&Bs[k][tx * 8];
            float4 b1 = *(const float4*)&Bs[k][tx * 8 + 4];
            float aa[8] = {a0.x, a0.y, a0.z, a0.w, a1.x, a1.y, a1.z, a1.w};
            float bb[8] = {b0.x, b0.y, b0.z, b0.w, b1.x, b1.y, b1.z, b1.w};
#pragma unroll
            for (int i = 0; i < 8; i++)
#pragma unroll
                for (int j = 0; j < 8; j++) acc[i][j] += aa[i] * bb[j];
        }
        __syncthreads();
    }
#pragma unroll
    for (int i = 0; i < 8; i++) {
        float4 o0 = {acc[i][0], acc[i][1], acc[i][2], acc[i][3]};
        float4 o1 = {acc[i][4], acc[i][5], acc[i][6], acc[i][7]};
        float* dst = &g_Iext[(size_t)(m0 + ty * 8 + i) * NH + n0 + tx * 8];
        *(float4*)dst = o0;
        *(float4*)(dst + 4) = o1;
    }
}

// -------- grid barrier (all NBLK CTAs co-resident) --------
__device__ __forceinline__ void grid_sync(int step) {
    __syncthreads();
    if (threadIdx.x == 0) {
        __threadfence();                       // release prior spike writes
        atomicAdd(&g_bar, 1u);
        const unsigned target = (unsigned)(step + 1) * NBLK;
        unsigned cur;
        do {
            asm volatile("ld.global.acquire.gpu.u32 %0, [%1];"
                         : "=r"(cur) : "l"(&g_bar));
        } while (cur < target);
    }
    __syncthreads();
}

// butterfly reduction stage: after all 5 stages, lane L holds output L in a[0]
#define RSTAGE(M, NHALF)                                                        \
    if (ln & (M)) {                                                             \
        _Pragma("unroll")                                                       \
        for (int i = 0; i < (NHALF); i++) {                                     \
            float tmp = a[i]; a[i] = a[i + (NHALF)]; a[i + (NHALF)] = tmp;      \
        }                                                                       \
    }                                                                           \
    _Pragma("unroll")                                                           \
    for (int i = 0; i < (NHALF); i++)                                           \
        a[i] += __shfl_xor_sync(0xffffffffu, a[i + (NHALF)], (M));

// -------- Phase B: persistent scan --------
__global__ __launch_bounds__(256, 1) void scan_kernel(const float* __restrict__ Wrec) {
    __shared__ float wt_s[8 * NH];     // 32 KB: this CTA's 8 W_rec rows

    const int tid = threadIdx.x;
    const int w  = tid >> 5;           // warp 0..7 -> batches [4w, 4w+4)
    const int ln = tid & 31;
    const int c  = blockIdx.x;
    const int h0 = c * 8;

    // preload weights once (resident in smem for the whole scan)
#pragma unroll
    for (int i = 0; i < 8; i++) {
        int idx = tid + i * 256;                 // float4 index 0..2047
        int row = idx >> 8, col = idx & 255;
        ((float4*)wt_s)[idx] =
            ((const float4*)(Wrec + (size_t)(h0 + row) * NH))[col];
    }
    __syncthreads();

    // neuron ownership: lane ln of warp w owns (b, h)
    const int b = w * 4 + (ln >> 3);
    const int h = h0 + (ln & 7);

    float v = V_RST, a0 = 0.f, a1 = 0.f, ref = 0.f, hs = 0.f, psc = 0.f;
    int cnt = 0;

    for (int t = 0; t < T_STEPS; t++) {
        float Iv = g_Iext[((size_t)t * BATCH + b) * NH + h];   // prefetch early

        if (t > 0) {
            const float4* sp = (const float4*)g_spkf[(t - 1) & 1];
            float a[32];
#pragma unroll
            for (int i = 0; i < 32; i++) a[i] = 0.f;

            // K-slice of this lane: float4 index (ln + u*32) within each row
            float4 s[4];
#pragma unroll
            for (int bb = 0; bb < 4; bb++)
                s[bb] = __ldcg(&sp[(w * 4 + bb) * 256 + ln]);

#pragma unroll
            for (int u = 0; u < 8; u++) {
                float4 sn[4];
                if (u < 7) {
#pragma unroll
                    for (int bb = 0; bb < 4; bb++)
                        sn[bb] = __ldcg(&sp[(w * 4 + bb) * 256 + ln + (u + 1) * 32]);
                }
#pragma unroll
                for (int hh = 0; hh < 8; hh++) {
                    float4 wv = ((const float4*)wt_s)[hh * 256 + ln + u * 32];
#pragma unroll
                    for (int bb = 0; bb < 4; bb++) {
                        float acc = a[bb * 8 + hh];
                        acc += s[bb].x * wv.x;
                        acc += s[bb].y * wv.y;
                        acc += s[bb].z * wv.z;
                        acc += s[bb].w * wv.w;
                        a[bb * 8 + hh] = acc;
                    }
                }
#pragma unroll
                for (int bb = 0; bb < 4; bb++) s[bb] = sn[bb];
            }

            // reduce 32 partial outputs across the warp
            RSTAGE(16, 16)
            RSTAGE(8, 8)
            RSTAGE(4, 4)
            RSTAGE(2, 2)
            RSTAGE(1, 1)
            float rec = a[0];

            hs  = D_SYN * hs + rec;
            psc = D_SYN * psc + hs;          // DT = 1
        }

        // GLIF3 neuron update
        float I = Iv + psc;
        a0 *= D_A0;
        a1 *= D_A1;
        v = v + ((V_RST - v) * (1.0f / 20.0f) + (I + a0 + a1) * 0.5f);
        bool in_ref = ref > 0.0f;
        if (in_ref) v = V_RST;
        float spike = (!in_ref && v >= V_TH) ? 1.0f : 0.0f;
        if (spike > 0.0f) {
            v = V_RST; a0 += 1.0f; a1 -= 2.0f; ref = 2.0f; cnt++;
        } else {
            ref = fmaxf(ref - 1.0f, 0.0f);
        }
        g_spkf[t & 1][b * NH + h] = spike;

        grid_sync(t);
    }
    g_rate[b * NH + h] = (float)cnt * 0.001f;
}

// -------- Phase C: out[b,o] = rate[b,:] . W_out[o,:] --------
__global__ __launch_bounds__(256) void out_kernel(const float* __restrict__ Wout,
                                                  float* __restrict__ out) {
    int gw   = (blockIdx.x * blockDim.x + threadIdx.x) >> 5;
    int lane = threadIdx.x & 31;
    int b = gw >> 8;
    int o = gw & 255;
    const float* r = &g_rate[b * NH];
    const float* wp = &Wout[(size_t)o * NH];
    float s = 0.f;
    for (int hh = lane; hh < NH; hh += 32) s += r[hh] * wp[hh];
#pragma unroll
    for (int off = 16; off; off >>= 1) s += __shfl_down_sync(0xffffffffu, s, off);
    if (lane == 0) out[b * NO + o] = s;
}

// -------- launch --------
extern "C" void kernel_launch(void* const* d_in, const int* in_sizes, int n_in,
                              void* d_out, int out_size) {
    const float* x = nullptr;
    const float* W_in = nullptr;
    const float* W_rec = nullptr;
    const float* W_out = nullptr;
    for (int i = 0; i < n_in; i++) {
        switch (in_sizes[i]) {
            case T_STEPS * BATCH * NI: x     = (const float*)d_in[i]; break;
            case NH * NI:              W_in  = (const float*)d_in[i]; break;
            case NH * NH:              W_rec = (const float*)d_in[i]; break;
            case NO * NH:              W_out = (const float*)d_in[i]; break;
        }
    }
    float* out = (float*)d_out;

    init_kernel<<<1, 1>>>();

    dim3 g1(NH / BN, (T_STEPS * BATCH) / BM);   // (8, 250)
    gemm_in_kernel<<<g1, 256>>>(x, W_in);

    scan_kernel<<<NBLK, 256>>>(W_rec);

    out_kernel<<<(BATCH * NO * 32) / 256, 256>>>(W_out, out);
}

// round 4
// speedup vs baseline: 2.7837x; 1.0024x over previous
#include <cuda_runtime.h>

// MinimalRSNN: GLIF3 + AlphaPSC recurrent SNN.
//   Phase A: I_ext = x @ W_in^T   (fp32 SGEMM, 128x128x8, f32x2 packed FMA)
//   Phase B: persistent 1000-step scan, 128 CTAs, 1 grid barrier/step
//            recurrent GEMM: warp tile 8b x 4h, K-split 32, k-parity f32x2
//            accumulators, spikes as bf16 (exact 0/1) streamed from L2,
//            W_rec slice resident in smem
//   Phase C: out = spike_rate @ W_out^T

#define T_STEPS 1000
#define BATCH   32
#define NI      512
#define NH      1024
#define NO      256

#define V_TH   (-45.0f)
#define V_RST  (-60.0f)
#define D_SYN  0.8187307530779818f   // exp(-1/5)
#define D_A0   0.9048374180359595f   // exp(-0.1)
#define D_A1   0.8187307530779818f   // exp(-0.2)

#define NBLK  128

// packed fp32 helpers (Blackwell f32x2 pipe)
#define FMA2(d, a, b)  asm("fma.rn.f32x2 %0, %1, %2, %0;" : "+l"(d) : "l"(a), "l"(b))
#define PACK2(d, lo, hi) asm("mov.b64 %0, {%1, %2};" : "=l"(d) : "r"(lo), "r"(hi))
#define UNPK2(lo, hi, s) asm("mov.b64 {%0, %1}, %2;" : "=r"(lo), "=r"(hi) : "l"(s))

typedef unsigned long long u64;
typedef unsigned int       u32;

// -------- device scratch (no allocations allowed) --------
__device__ float          g_Iext[(size_t)T_STEPS * BATCH * NH];   // 131 MB
__device__ unsigned short g_spk16[2][BATCH * NH];                 // bf16 spikes, double-buffered
__device__ float          g_rate[BATCH * NH];
__device__ unsigned int   g_bar;

__global__ void init_kernel() { g_bar = 0u; }

// -------- Phase A: C[M,N] = A[M,K] * B[N,K]^T (fp32, f32x2 inner) --------
#define BM 128
#define BN 128
#define BK 8
__global__ __launch_bounds__(256, 2) void gemm_in_kernel(const float* __restrict__ A,
                                                         const float* __restrict__ Bm) {
    __shared__ float As[BK][BM];
    __shared__ float Bs[BK][BN];
    const int tid = threadIdx.x;
    const int m0 = blockIdx.y * BM, n0 = blockIdx.x * BN;
    const int lr = tid >> 1;          // 0..127
    const int lc = (tid & 1) * 4;     // 0 or 4
    const int tx = tid & 15, ty = tid >> 4;
    u64 acc[8][4];
#pragma unroll
    for (int i = 0; i < 8; i++)
#pragma unroll
        for (int j = 0; j < 4; j++) acc[i][j] = 0ull;

    for (int kc = 0; kc < NI; kc += BK) {
        float4 av = *(const float4*)&A [(size_t)(m0 + lr) * NI + kc + lc];
        float4 bv = *(const float4*)&Bm[(size_t)(n0 + lr) * NI + kc + lc];
        As[lc + 0][lr] = av.x; As[lc + 1][lr] = av.y;
        As[lc + 2][lr] = av.z; As[lc + 3][lr] = av.w;
        Bs[lc + 0][lr] = bv.x; Bs[lc + 1][lr] = bv.y;
        Bs[lc + 2][lr] = bv.z; Bs[lc + 3][lr] = bv.w;
        __syncthreads();
#pragma unroll
        for (int k = 0; k < BK; k++) {
            float4 a0 = *(const float4*)&As[k][ty * 8];
            float4 a1 = *(const float4*)&As[k][ty * 8 + 4];
            ulonglong2 bp = *(const ulonglong2*)&Bs[k][tx * 8];
            ulonglong2 bq = *(const ulonglong2*)&Bs[k][tx * 8 + 4];
            float aa[8] = {a0.x, a0.y, a0.z, a0.w, a1.x, a1.y, a1.z, a1.w};
            u64 ap[8];
#pragma unroll
            for (int i = 0; i < 8; i++) {
                u32 ab = __float_as_uint(aa[i]);
                PACK2(ap[i], ab, ab);
            }
#pragma unroll
            for (int i = 0; i < 8; i++) {
                FMA2(acc[i][0], ap[i], bp.x);
                FMA2(acc[i][1], ap[i], bp.y);
                FMA2(acc[i][2], ap[i], bq.x);
                FMA2(acc[i][3], ap[i], bq.y);
            }
        }
        __syncthreads();
    }
#pragma unroll
    for (int i = 0; i < 8; i++) {
        float o[8];
#pragma unroll
        for (int j = 0; j < 4; j++) {
            u32 lo, hi;
            UNPK2(lo, hi, acc[i][j]);
            o[2 * j]     = __uint_as_float(lo);
            o[2 * j + 1] = __uint_as_float(hi);
        }
        float4 o0 = {o[0], o[1], o[2], o[3]};
        float4 o1 = {o[4], o[5], o[6], o[7]};
        float* dst = &g_Iext[(size_t)(m0 + ty * 8 + i) * NH + n0 + tx * 8];
        *(float4*)dst = o0;
        *(float4*)(dst + 4) = o1;
    }
}

// -------- grid barrier (all NBLK CTAs co-resident) --------
__device__ __forceinline__ void grid_sync(int step) {
    __syncthreads();
    if (threadIdx.x == 0) {
        __threadfence();                       // release prior spike writes
        atomicAdd(&g_bar, 1u);
        const unsigned target = (unsigned)(step + 1) * NBLK;
        unsigned cur;
        do {
            asm volatile("ld.global.acquire.gpu.u32 %0, [%1];"
                         : "=r"(cur) : "l"(&g_bar));
        } while (cur < target);
    }
    __syncthreads();
}

// butterfly reduction stage over 32 values: after 5 stages lane L holds sum L in a[0]
#define RSTAGE(M, NHALF)                                                        \
    if (ln & (M)) {                                                             \
        _Pragma("unroll")                                                       \
        for (int i = 0; i < (NHALF); i++) {                                     \
            float tmp = a[i]; a[i] = a[i + (NHALF)]; a[i + (NHALF)] = tmp;      \
        }                                                                       \
    }                                                                           \
    _Pragma("unroll")                                                           \
    for (int i = 0; i < (NHALF); i++)                                           \
        a[i] += __shfl_xor_sync(0xffffffffu, a[i + (NHALF)], (M));

// -------- Phase B: persistent scan --------
__global__ __launch_bounds__(256, 1) void scan_kernel(const float* __restrict__ Wrec) {
    __shared__ float wt[8 * NH];       // 32 KB: this CTA's 8 W_rec rows (contiguous)

    const int tid = threadIdx.x;
    const int w  = tid >> 5;
    const int ln = tid & 31;
    const int c  = blockIdx.x;
    const int h0 = c * 8;
    const int bg = w >> 1;             // batch group: batches [8bg, 8bg+8)
    const int hg = w & 1;              // h group: rows [4hg, 4hg+4) of the slice

    // preload weights once (rows h0..h0+7 are contiguous in Wrec)
    {
        const float4* src = (const float4*)(Wrec + (size_t)h0 * NH);
#pragma unroll
        for (int i = 0; i < 8; i++)
            ((float4*)wt)[tid + i * 256] = src[tid + i * 256];
    }
    __syncthreads();

    // neuron ownership (butterfly maps lane ln -> index ln = bb*4+hh)
    const int b = 8 * bg + (ln >> 2);
    const int h = h0 + 4 * hg + (ln & 3);

    const float* wbase = wt + (4 * hg) * NH + 4 * ln;   // + hh*NH + 128*u

    float v = V_RST, a0 = 0.f, a1 = 0.f, ref = 0.f, hs = 0.f, psc = 0.f;
    int cnt = 0;
    float Iv = __ldcg(&g_Iext[(size_t)b * NH + h]);     // I_ext(t=0)

    for (int t = 0; t < T_STEPS; t++) {
        if (t > 0) {
            const char* sp = (const char*)g_spk16[(t - 1) & 1];
            u64 acc[32];
#pragma unroll
            for (int i = 0; i < 32; i++) acc[i] = 0ull;

            // lane's k-slice: k = 4*ln + 128*u; bf16 byte offset = 8*ln + 256*u
            uint2 s[8], sn[8];
#pragma unroll
            for (int bb = 0; bb < 8; bb++)
                s[bb] = __ldcg((const uint2*)(sp + (8 * bg + bb) * (NH * 2) + 8 * ln));

#pragma unroll
            for (int u = 0; u < 8; u++) {
                if (u < 7) {
#pragma unroll
                    for (int bb = 0; bb < 8; bb++)
                        sn[bb] = __ldcg((const uint2*)(sp + (8 * bg + bb) * (NH * 2)
                                                          + 8 * ln + 256 * (u + 1)));
                }
                // bf16 pairs -> f32x2 (bf16 is top half of f32: pure bit ops)
                u64 p0[8], p1[8];
#pragma unroll
                for (int bb = 0; bb < 8; bb++) {
                    PACK2(p0[bb], s[bb].x << 16, s[bb].x & 0xFFFF0000u);
                    PACK2(p1[bb], s[bb].y << 16, s[bb].y & 0xFFFF0000u);
                }
#pragma unroll
                for (int hh = 0; hh < 4; hh++) {
                    ulonglong2 wv = *(const ulonglong2*)(wbase + hh * NH + 128 * u);
#pragma unroll
                    for (int bb = 0; bb < 8; bb++) {
                        FMA2(acc[bb * 4 + hh], p0[bb], wv.x);
                        FMA2(acc[bb * 4 + hh], p1[bb], wv.y);
                    }
                }
#pragma unroll
                for (int bb = 0; bb < 8; bb++) s[bb] = sn[bb];
            }

            // fold k-parity halves, then butterfly across the warp
            float a[32];
#pragma unroll
            for (int i = 0; i < 32; i++) {
                u32 lo, hi;
                UNPK2(lo, hi, acc[i]);
                a[i] = __uint_as_float(lo) + __uint_as_float(hi);
            }
            RSTAGE(16, 16)
            RSTAGE(8, 8)
            RSTAGE(4, 4)
            RSTAGE(2, 2)
            RSTAGE(1, 1)
            float rec = a[0];

            hs  = D_SYN * hs + rec;
            psc = D_SYN * psc + hs;          // DT = 1
        }

        // GLIF3 neuron update (all state in registers)
        float I = Iv + psc;
        a0 *= D_A0;
        a1 *= D_A1;
        v = v + ((V_RST - v) * (1.0f / 20.0f) + (I + a0 + a1) * 0.5f);
        bool in_ref = ref > 0.0f;
        if (in_ref) v = V_RST;
        float spike = (!in_ref && v >= V_TH) ? 1.0f : 0.0f;
        unsigned short s16;
        if (spike > 0.0f) {
            v = V_RST; a0 += 1.0f; a1 -= 2.0f; ref = 2.0f; cnt++;
            s16 = 0x3F80;                    // bf16 1.0
        } else {
            ref = fmaxf(ref - 1.0f, 0.0f);
            s16 = 0;
        }
        g_spk16[t & 1][b * NH + h] = s16;

        // prefetch next step's external current (overlaps barrier wait)
        int tn = (t < T_STEPS - 1) ? t + 1 : t;
        Iv = __ldcg(&g_Iext[((size_t)tn * BATCH + b) * NH + h]);

        grid_sync(t);
    }
    g_rate[b * NH + h] = (float)cnt * 0.001f;
}

// -------- Phase C: out[b,o] = rate[b,:] . W_out[o,:] --------
__global__ __launch_bounds__(256) void out_kernel(const float* __restrict__ Wout,
                                                  float* __restrict__ out) {
    int gw   = (blockIdx.x * blockDim.x + threadIdx.x) >> 5;
    int lane = threadIdx.x & 31;
    int b = gw >> 8;
    int o = gw & 255;
    const float* r = &g_rate[b * NH];
    const float* wp = &Wout[(size_t)o * NH];
    float s = 0.f;
    for (int hh = lane; hh < NH; hh += 32) s += r[hh] * wp[hh];
#pragma unroll
    for (int off = 16; off; off >>= 1) s += __shfl_down_sync(0xffffffffu, s, off);
    if (lane == 0) out[b * NO + o] = s;
}

// -------- launch --------
extern "C" void kernel_launch(void* const* d_in, const int* in_sizes, int n_in,
                              void* d_out, int out_size) {
    const float* x = nullptr;
    const float* W_in = nullptr;
    const float* W_rec = nullptr;
    const float* W_out = nullptr;
    for (int i = 0; i < n_in; i++) {
        switch (in_sizes[i]) {
            case T_STEPS * BATCH * NI: x     = (const float*)d_in[i]; break;
            case NH * NI:              W_in  = (const float*)d_in[i]; break;
            case NH * NH:              W_rec = (const float*)d_in[i]; break;
            case NO * NH:              W_out = (const float*)d_in[i]; break;
        }
    }
    float* out = (float*)d_out;

    init_kernel<<<1, 1>>>();

    dim3 g1(NH / BN, (T_STEPS * BATCH) / BM);   // (8, 250)
    gemm_in_kernel<<<g1, 256>>>(x, W_in);

    scan_kernel<<<NBLK, 256>>>(W_rec);

    out_kernel<<<(BATCH * NO * 32) / 256, 256>>>(W_out, out);
}